// round 8
// baseline (speedup 1.0000x reference)
#include <cuda_runtime.h>

// PManifold: B=64, H=2, N=512, K=64, M=16  — fused single kernel, R8.
// output (b,h,k',m) = log0(exp0( sum over a of log0(exp0(point n)+theta_k) ))
// with k = a>>3, n = (a&7)*64 + k' (reference's reshape scramble).
// Collapse: v_m = A0*[m==0] + A1*[m==1] + sum_k F_k*theta_k[m];
// log0(exp0(v)) == min(||v||, atanh(MX))/||v|| * v exactly.
// R8: dead-clip removal (range analysis: s <= 0.956 << MAXN^2, all terms of s
// are >= 0 so EPS folds into the Dk constant), balanced exp0 prologue.

#define B_ 64
#define H_ 2
#define N_ 512
#define K_ 64
#define M_ 16

#define EPS2_ 1e-14f
// atanh(fp32(1-1e-5)) computed in double precision (epilogue clip only)
#define ATMX_ 6.1023535f
// 0.5 * ln(2)
#define HALF_LN2_ 0.34657359027997264f

__global__ __launch_bounds__(256, 7) void pm_fused(const float* __restrict__ in,
                                                   const float* __restrict__ theta,
                                                   float* __restrict__ out)
{
    __shared__ float4 e_pts[8][8];        // [r][k'-kbase]: (e0,e1,q,0)
    __shared__ float  th_t[M_][68];       // transposed theta: [m][k], pad 68
    __shared__ float4 tk_s[K_];           // per-k (2*t0, 2*t1, Dk+EPS2, 0)
    __shared__ float  F_sh[8][K_];        // per-warp F_k

    const int bh    = blockIdx.x >> 3;          // b*2 + h
    const int kbase = (blockIdx.x & 7) << 3;    // k' block base
    const int h     = bh & 1;
    const int tid   = threadIdx.x;
    const int w     = tid >> 5;
    const int lane  = tid & 31;

    // ---- prologue: theta staging (transposed) + per-k constants ----
    {
        float4 tv = reinterpret_cast<const float4*>(theta + h * (K_ * M_))[tid];
        int k = tid >> 2, q = tid & 3;            // thread holds theta_k[4q..4q+3]
        th_t[4 * q + 0][k] = tv.x;
        th_t[4 * q + 1][k] = tv.y;
        th_t[4 * q + 2][k] = tv.z;
        th_t[4 * q + 3][k] = tv.w;
        // Dk = sum_m theta_k[m]^2 over the 4 threads of row k (+EPS2 guard folded)
        float p = fmaf(tv.x, tv.x, fmaf(tv.y, tv.y, fmaf(tv.z, tv.z, tv.w * tv.w)));
        p += __shfl_xor_sync(0xffffffffu, p, 1);
        p += __shfl_xor_sync(0xffffffffu, p, 2);
        if (q == 0) tk_s[k] = make_float4(tv.x + tv.x, tv.y + tv.y, p + EPS2_, 0.0f);
    }

    // ---- prologue: exp0 for this block's 64 points, spread over all 8 warps ----
    if (lane < 8) {
        int idx = w * 8 + lane;                   // 0..63
        int r = idx >> 3, j = idx & 7;
        float2 d = reinterpret_cast<const float2*>(in)[bh * N_ + r * 64 + kbase + j];
        float s   = fmaf(d.x, d.x, fmaf(d.y, d.y, EPS2_));
        float rin = rsqrtf(s);
        float n   = s * rin;                      // ||d||
        // tanh(n)/n: exp-based for normal n, series for tiny n (cancellation)
        float e2  = __expf(n + n);
        float big = (1.0f - __fdividef(2.0f, e2 + 1.0f)) * rin;
        float sml = fmaf(s, fmaf(s, 2.0f / 15.0f, -1.0f / 3.0f), 1.0f);
        float sc  = (s < 1e-3f) ? sml : big;
        e_pts[r][j] = make_float4(d.x * sc, d.y * sc, (sc * sc) * s, 0.0f);
    }
    __syncthreads();

    // ---- main: warp w owns output k' = kbase + w; lane owns theta rows
    //      k = lane and k = lane + 32 ----
    const float4 ca = tk_s[lane];         // (2t0a, 2t1a, Da+eps, -)
    const float4 cb = tk_s[lane + 32];    // (2t0b, 2t1b, Db+eps, -)

    float Fa = 0.0f, Fb = 0.0f, A0 = 0.0f, A1 = 0.0f;
    #pragma unroll
    for (int r = 0; r < 8; ++r) {
        float4 e = e_pts[r][w];           // warp-broadcast LDS.128
        // s = ||x||^2 + eps = q + 2 t0 e0 + 2 t1 e1 + (Dk + eps); all terms >= 0
        float sA = fmaf(ca.x, e.x, fmaf(ca.y, e.y, e.z)) + ca.z;
        float sB = fmaf(cb.x, e.x, fmaf(cb.y, e.y, e.z)) + cb.z;
        float riA = rsqrtf(sA), riB = rsqrtf(sB);   // 1/||x||
        float rA  = sA * riA;                       // ||x||  (provably < 0.98)
        float rB  = sB * riB;
        // f' = (log2(1+r) - log2(1-r)) / ||x||   (0.5*ln2 deferred)
        float fA = (__log2f(1.0f + rA) - __log2f(1.0f - rA)) * riA;
        float fB = (__log2f(1.0f + rB) - __log2f(1.0f - rB)) * riB;
        Fa += fA;
        Fb += fB;
        float fs = fA + fB;
        A0 = fmaf(fs, e.x, A0);
        A1 = fmaf(fs, e.y, A1);
    }

    // A0/A1 full-warp butterfly (covers all k, all r)
    #pragma unroll
    for (int o = 16; o; o >>= 1) {
        A0 += __shfl_xor_sync(0xffffffffu, A0, o);
        A1 += __shfl_xor_sync(0xffffffffu, A1, o);
    }

    F_sh[w][lane]      = Fa;
    F_sh[w][lane + 32] = Fb;
    __syncwarp();

    // matvec: v_m = sum_k F_k * theta_k[m]; two lanes per m split the k-range,
    // vectorized: 8 x (2 LDS.128 + 4 FMA)
    const int m  = lane & 15;
    const int hk = lane >> 4;
    const float4* t4p = reinterpret_cast<const float4*>(&th_t[m][hk * 32]);
    const float4* f4p = reinterpret_cast<const float4*>(&F_sh[w][hk * 32]);
    float acc = 0.0f;
    #pragma unroll
    for (int j = 0; j < 8; ++j) {
        float4 t4 = t4p[j];
        float4 f4 = f4p[j];
        acc = fmaf(f4.x, t4.x, acc);
        acc = fmaf(f4.y, t4.y, acc);
        acc = fmaf(f4.z, t4.z, acc);
        acc = fmaf(f4.w, t4.w, acc);
    }
    acc += __shfl_xor_sync(0xffffffffu, acc, 16);

    float v = acc;
    if (lane == 0) v += A0;
    if (lane == 1) v += A1;
    v *= HALF_LN2_;

    // ||v||^2 across the 16 components (butterfly within 16-lane halves)
    float ns2 = fmaf(v, v, EPS2_);
    #pragma unroll
    for (int o = 8; o; o >>= 1) ns2 += __shfl_xor_sync(0xffffffffu, ns2, o);
    float rin   = rsqrtf(ns2);
    float ns    = ns2 * rin;
    float scale = fminf(ns, ATMX_) * rin;   // log0(exp0(v)) scale, exact

    if (lane < 16)
        out[(bh * K_ + kbase + w) * M_ + lane] = scale * v;
}

extern "C" void kernel_launch(void* const* d_in, const int* in_sizes, int n_in,
                              void* d_out, int out_size)
{
    const float* inputs = (const float*)d_in[0];   // (B,H,N,2)
    const float* theta  = (const float*)d_in[1];   // (H,K,M)
    float* out = (float*)d_out;                    // (B,2,K,M)

    pm_fused<<<(B_ * H_ * K_) / 8, 256>>>(inputs, theta, out);
}

// round 9
// speedup vs baseline: 1.0208x; 1.0208x over previous
#include <cuda_runtime.h>

// PManifold: B=64, H=2, N=512, K=64, M=16  — fused single kernel, R9.
// output (b,h,k',m) = log0(exp0( sum over a of log0(exp0(point n)+theta_k) ))
// with k = a>>3, n = (a&7)*64 + k' (reference's reshape scramble).
// Collapse: v_m = A0*[m==0] + A1*[m==1] + sum_k F_k*theta_k[m];
// log0(exp0(v)) == min(||v||, atanh(MX))/||v|| * v exactly.
// R9: grid 512, 16 outputs per block, 2 adjacent outputs per warp —
// amortizes theta staging / constants / barriers across 2x the work.

#define B_ 64
#define H_ 2
#define N_ 512
#define K_ 64
#define M_ 16

#define EPS2_ 1e-14f
// atanh(fp32(1-1e-5)) in double precision (epilogue clip only)
#define ATMX_ 6.1023535f
// 0.5 * ln(2)
#define HALF_LN2_ 0.34657359027997264f

__global__ __launch_bounds__(256, 4) void pm_fused(const float* __restrict__ in,
                                                   const float* __restrict__ theta,
                                                   float* __restrict__ out)
{
    __shared__ float4 e_pts[8][16];       // [r][k'-kbase]: (e0,e1,q,0)
    __shared__ float  th_t[M_][68];       // transposed theta: [m][k], pad 68
    __shared__ float4 tk_s[K_];           // per-k (2*t0, 2*t1, Dk+EPS2, 0)
    __shared__ float  F_sh[16][K_];       // [local output][k]

    const int bh    = blockIdx.x >> 2;          // b*2 + h
    const int kbase = (blockIdx.x & 3) << 4;    // k' block base (16 outputs)
    const int h     = bh & 1;
    const int tid   = threadIdx.x;
    const int w     = tid >> 5;
    const int lane  = tid & 31;

    // ---- prologue: theta staging (transposed) + per-k constants ----
    {
        float4 tv = reinterpret_cast<const float4*>(theta + h * (K_ * M_))[tid];
        int k = tid >> 2, q = tid & 3;            // thread holds theta_k[4q..4q+3]
        th_t[4 * q + 0][k] = tv.x;
        th_t[4 * q + 1][k] = tv.y;
        th_t[4 * q + 2][k] = tv.z;
        th_t[4 * q + 3][k] = tv.w;
        // Dk = sum_m theta_k[m]^2 over the 4 threads of row k (+EPS2 folded)
        float p = fmaf(tv.x, tv.x, fmaf(tv.y, tv.y, fmaf(tv.z, tv.z, tv.w * tv.w)));
        p += __shfl_xor_sync(0xffffffffu, p, 1);
        p += __shfl_xor_sync(0xffffffffu, p, 2);
        if (q == 0) tk_s[k] = make_float4(tv.x + tv.x, tv.y + tv.y, p + EPS2_, 0.0f);
    }

    // ---- prologue: exp0 for this block's 128 points ----
    if (tid < 128) {
        int r = tid >> 4, j = tid & 15;
        float2 d = reinterpret_cast<const float2*>(in)[bh * N_ + r * 64 + kbase + j];
        float s   = fmaf(d.x, d.x, fmaf(d.y, d.y, EPS2_));
        float rin = rsqrtf(s);
        float n   = s * rin;                      // ||d||
        float e2  = __expf(n + n);
        float big = (1.0f - __fdividef(2.0f, e2 + 1.0f)) * rin;
        float sml = fmaf(s, fmaf(s, 2.0f / 15.0f, -1.0f / 3.0f), 1.0f);
        float sc  = (s < 1e-3f) ? sml : big;
        e_pts[r][j] = make_float4(d.x * sc, d.y * sc, (sc * sc) * s, 0.0f);
    }
    __syncthreads();

    // ---- main: warp w owns outputs k' = kbase+2w (X) and kbase+2w+1 (Y);
    //      lane owns theta rows k = lane and k = lane + 32 ----
    const float4 ca = tk_s[lane];
    const float4 cb = tk_s[lane + 32];

    float FaX = 0.0f, FbX = 0.0f, FaY = 0.0f, FbY = 0.0f;
    float A0X = 0.0f, A1X = 0.0f, A0Y = 0.0f, A1Y = 0.0f;

    #pragma unroll
    for (int r = 0; r < 8; ++r) {
        float4 eX = e_pts[r][2 * w];       // warp-broadcast LDS.128
        float4 eY = e_pts[r][2 * w + 1];
        // s = q + 2 t0 e0 + 2 t1 e1 + (Dk + eps); all terms >= 0, s < 0.956
        float sXa = fmaf(ca.x, eX.x, fmaf(ca.y, eX.y, eX.z)) + ca.z;
        float sXb = fmaf(cb.x, eX.x, fmaf(cb.y, eX.y, eX.z)) + cb.z;
        float sYa = fmaf(ca.x, eY.x, fmaf(ca.y, eY.y, eY.z)) + ca.z;
        float sYb = fmaf(cb.x, eY.x, fmaf(cb.y, eY.y, eY.z)) + cb.z;
        float riXa = rsqrtf(sXa), riXb = rsqrtf(sXb);
        float riYa = rsqrtf(sYa), riYb = rsqrtf(sYb);
        float rXa = sXa * riXa, rXb = sXb * riXb;
        float rYa = sYa * riYa, rYb = sYb * riYb;
        // f = (log2(1+r) - log2(1-r)) / ||x||   (0.5*ln2 deferred)
        float fXa = (__log2f(1.0f + rXa) - __log2f(1.0f - rXa)) * riXa;
        float fXb = (__log2f(1.0f + rXb) - __log2f(1.0f - rXb)) * riXb;
        float fYa = (__log2f(1.0f + rYa) - __log2f(1.0f - rYa)) * riYa;
        float fYb = (__log2f(1.0f + rYb) - __log2f(1.0f - rYb)) * riYb;
        FaX += fXa;  FbX += fXb;
        FaY += fYa;  FbY += fYb;
        float fsX = fXa + fXb, fsY = fYa + fYb;
        A0X = fmaf(fsX, eX.x, A0X);  A1X = fmaf(fsX, eX.y, A1X);
        A0Y = fmaf(fsY, eY.x, A0Y);  A1Y = fmaf(fsY, eY.y, A1Y);
    }

    // A0/A1 full-warp butterflies (cover all k via lane-halves, all r)
    #pragma unroll
    for (int o = 16; o; o >>= 1) {
        A0X += __shfl_xor_sync(0xffffffffu, A0X, o);
        A1X += __shfl_xor_sync(0xffffffffu, A1X, o);
        A0Y += __shfl_xor_sync(0xffffffffu, A0Y, o);
        A1Y += __shfl_xor_sync(0xffffffffu, A1Y, o);
    }

    F_sh[2 * w][lane]          = FaX;
    F_sh[2 * w][lane + 32]     = FbX;
    F_sh[2 * w + 1][lane]      = FaY;
    F_sh[2 * w + 1][lane + 32] = FbY;
    __syncwarp();

    // matvec: lane owns one (output o, component m); full 64-k dot product.
    const int o = lane >> 4;               // 0 -> X, 1 -> Y
    const int m = lane & 15;
    const float4* t4p = reinterpret_cast<const float4*>(&th_t[m][0]);
    const float4* f4p = reinterpret_cast<const float4*>(&F_sh[2 * w + o][0]);
    float acc = 0.0f;
    #pragma unroll
    for (int j = 0; j < 16; ++j) {
        float4 t4 = t4p[j];
        float4 f4 = f4p[j];
        acc = fmaf(f4.x, t4.x, acc);
        acc = fmaf(f4.y, t4.y, acc);
        acc = fmaf(f4.z, t4.z, acc);
        acc = fmaf(f4.w, t4.w, acc);
    }

    float A0 = o ? A0Y : A0X;
    float A1 = o ? A1Y : A1X;
    float v = acc;
    if (m == 0) v += A0;
    if (m == 1) v += A1;
    v *= HALF_LN2_;

    // ||v||^2 over the 16 components of this output (xor stays within halves)
    float ns2 = fmaf(v, v, EPS2_);
    #pragma unroll
    for (int off = 8; off; off >>= 1) ns2 += __shfl_xor_sync(0xffffffffu, ns2, off);
    float rin   = rsqrtf(ns2);
    float ns    = ns2 * rin;
    float scale = fminf(ns, ATMX_) * rin;   // log0(exp0(v)) scale, exact

    // coalesced: 32 lanes cover 2 adjacent outputs x 16 components = 128B
    out[(bh * K_ + kbase + 2 * w) * M_ + lane] = scale * v;
}

extern "C" void kernel_launch(void* const* d_in, const int* in_sizes, int n_in,
                              void* d_out, int out_size)
{
    const float* inputs = (const float*)d_in[0];   // (B,H,N,2)
    const float* theta  = (const float*)d_in[1];   // (H,K,M)
    float* out = (float*)d_out;                    // (B,2,K,M)

    pm_fused<<<(B_ * H_ * K_) / 16, 256>>>(inputs, theta, out);
}